// round 1
// baseline (speedup 1.0000x reference)
#include <cuda_runtime.h>

#define NN 50000
#define EE 800000
#define HH 64
#define RR 8
#define LL 3

// ---------------- scratch (static __device__, no allocs) ----------------
__device__ __align__(16) float g_h0[NN * HH];
__device__ __align__(16) float g_h1[NN * HH];
__device__ float g_asrc[NN * RR];
__device__ float g_adst[NN * RR];
__device__ float g_sc[EE];
__device__ __align__(16) float g_t[NN * RR * HH];   // 102.4 MB
__device__ unsigned g_mbits[RR];
__device__ float g_denom[RR];

// monotonic float<->uint encoding for atomicMax over signed floats
__device__ __forceinline__ unsigned fenc(float f) {
    unsigned u = __float_as_uint(f);
    return (u & 0x80000000u) ? ~u : (u | 0x80000000u);
}
__device__ __forceinline__ float fdec(unsigned u) {
    unsigned b = (u & 0x80000000u) ? (u ^ 0x80000000u) : ~u;
    return __uint_as_float(b);
}

// ---------------- zero t buffer + stats ----------------
__global__ void k_zero() {
    int i = blockIdx.x * blockDim.x + threadIdx.x;
    ((float4*)g_t)[i] = make_float4(0.f, 0.f, 0.f, 0.f);
    if (blockIdx.x == 0 && threadIdx.x < RR) {
        g_mbits[threadIdx.x] = 0u;
        g_denom[threadIdx.x] = 0.f;
    }
}

// ---------------- generic 64x64 GEMM: out[n,k] = act(sum_d A[n,d]*W[k,d] + b[k]) ----------------
__global__ void k_gemm64(const float* __restrict__ A, const float* __restrict__ W,
                         const float* __restrict__ b, float* __restrict__ out,
                         int nrows, int do_relu)
{
    __shared__ float sW[64 * 64];   // transposed + xor-swizzled: (k,h) -> [h*64 + (k^(h&31))]
    __shared__ float sA[32 * 64];
    int tid = threadIdx.x;
    int n0 = blockIdx.x * 32;

    for (int idx = tid; idx < 4096; idx += 256) {
        int k = idx >> 6, h = idx & 63;
        sW[h * 64 + (k ^ (h & 31))] = W[idx];
    }
    for (int idx = tid; idx < 2048; idx += 256) {
        int nl = idx >> 6, h = idx & 63;
        int n = n0 + nl;
        sA[idx] = (n < nrows) ? A[n * 64 + h] : 0.f;
    }
    __syncthreads();

    int tx = tid & 31, ty = tid >> 5;   // tx -> k, k+32 ; ty -> node group
    float a0[4] = {0.f, 0.f, 0.f, 0.f}, a1[4] = {0.f, 0.f, 0.f, 0.f};
#pragma unroll 4
    for (int h = 0; h < 64; h++) {
        int c = h * 64 + (tx ^ (h & 31));
        float w0 = sW[c];
        float w1 = sW[c + 32];
#pragma unroll
        for (int j = 0; j < 4; j++) {
            float av = sA[(ty + 8 * j) * 64 + h];
            a0[j] += av * w0;
            a1[j] += av * w1;
        }
    }
    float b0 = __ldg(&b[tx]), b1 = __ldg(&b[tx + 32]);
#pragma unroll
    for (int j = 0; j < 4; j++) {
        int n = n0 + ty + 8 * j;
        if (n < nrows) {
            float v0 = a0[j] + b0, v1 = a1[j] + b1;
            if (do_relu) { v0 = fmaxf(v0, 0.f); v1 = fmaxf(v1, 0.f); }
            out[n * 64 + tx]      = v0;
            out[n * 64 + tx + 32] = v1;
        }
    }
}

// ---------------- per-node attention projections a_src[n,r], a_dst[n,r] ----------------
__global__ void k_proj(const float* __restrict__ h, const float* __restrict__ Watt)
{
    // 128 threads, 8 nodes/block; thread = (nl = tid>>4, p = tid&15); r=p&7, side=p>>3
    __shared__ float sH[8 * 64];
    __shared__ float sW[64 * 16];   // [h*16 + p]
    int tid = threadIdx.x;
    int n0 = blockIdx.x * 8;

    for (int idx = tid; idx < 512; idx += 128) {
        int nl = idx >> 6, hh = idx & 63;
        int n = n0 + nl;
        sH[idx] = (n < NN) ? h[n * 64 + hh] : 0.f;
    }
    for (int idx = tid; idx < 1024; idx += 128) {
        int p = idx >> 6, hh = idx & 63;
        sW[hh * 16 + p] = Watt[(p & 7) * 128 + (p >> 3) * 64 + hh];
    }
    __syncthreads();

    int nl = tid >> 4, p = tid & 15;
    float acc = 0.f;
#pragma unroll 8
    for (int hh = 0; hh < 64; hh++)
        acc += sH[nl * 64 + hh] * sW[hh * 16 + p];

    int n = n0 + nl;
    if (n < NN) {
        int r = p & 7;
        if (p < 8) g_asrc[n * RR + r] = acc;
        else       g_adst[n * RR + r] = acc;
    }
}

// ---------------- edge scores + per-relation max ----------------
__global__ void k_scores(const int* __restrict__ ei, const int* __restrict__ et,
                         const float* __restrict__ batt)
{
    __shared__ unsigned smax[RR];
    int tid = threadIdx.x;
    int e = blockIdx.x * 256 + tid;
    if (tid < RR) smax[tid] = 0u;
    __syncthreads();
    if (e < EE) {
        int s = ei[e], d = ei[EE + e], r = et[e];
        float sc = g_asrc[s * RR + r] + g_adst[d * RR + r] + __ldg(&batt[r]);
        sc = (sc > 0.f) ? sc : 0.2f * sc;   // leaky relu
        g_sc[e] = sc;
        atomicMax(&smax[r], fenc(sc));
    }
    __syncthreads();
    if (tid < RR) atomicMax(&g_mbits[tid], smax[tid]);
}

// ---------------- exp(scores - max) + per-relation sum ----------------
__global__ void k_exp(const int* __restrict__ et)
{
    __shared__ float ssum[RR];
    __shared__ float sm[RR];
    int tid = threadIdx.x;
    int e = blockIdx.x * 256 + tid;
    if (tid < RR) { ssum[tid] = 0.f; sm[tid] = fdec(g_mbits[tid]); }
    __syncthreads();
    if (e < EE) {
        int r = et[e];
        float ex = expf(g_sc[e] - sm[r]);
        g_sc[e] = ex;
        atomicAdd(&ssum[r], ex);
    }
    __syncthreads();
    if (tid < RR) atomicAdd(&g_denom[tid], ssum[tid]);
}

// ---------------- scatter: t[dst,r,:] += att * h[src,:] (float4 vector atomics) ----------------
__global__ void k_scatter(const int* __restrict__ ei, const int* __restrict__ et,
                          const float* __restrict__ h)
{
    int tid = threadIdx.x;
    int grp = tid >> 4, lane = tid & 15;      // 16 lanes per edge, one float4 each
    int e = blockIdx.x * 16 + grp;
    if (e >= EE) return;
    int s = ei[e], d = ei[EE + e], r = et[e];
    float att = g_sc[e] / g_denom[r];
    float4 hv = __ldg((const float4*)(h + (size_t)s * 64) + lane);
    float4 v = make_float4(hv.x * att, hv.y * att, hv.z * att, hv.w * att);
    atomicAdd((float4*)(g_t + ((size_t)d * RR + r) * 64) + lane, v);
}

// ---------------- fused combine: agg GEMM + gate GEMM + gated mean + residual + LN + relu ----------------
__global__ void k_combine(const float* __restrict__ h,
                          const float* __restrict__ Wrel, const float* __restrict__ Wgate,
                          const float* __restrict__ bgate,
                          const float* __restrict__ gamma, const float* __restrict__ beta,
                          float* __restrict__ hout)
{
    __shared__ float sWr[64 * 64];   // transposed+swizzled per relation
    __shared__ float sWg[64 * 64];
    __shared__ float sT[32 * 64];
    __shared__ float sH[32 * 64];
    int tid = threadIdx.x;
    int n0 = blockIdx.x * 32;
    int tx = tid & 31, ty = tid >> 5;

    for (int idx = tid; idx < 2048; idx += 256) {
        int nl = idx >> 6, hh = idx & 63;
        int n = n0 + nl;
        sH[idx] = (n < NN) ? h[n * 64 + hh] : 0.f;
    }

    float acc0[4] = {0.f, 0.f, 0.f, 0.f}, acc1[4] = {0.f, 0.f, 0.f, 0.f};

    for (int r = 0; r < RR; r++) {
        __syncthreads();   // protect shared from previous iteration readers
        for (int idx = tid; idx < 4096; idx += 256) {
            int k = idx >> 6, hh = idx & 63;
            int col = hh * 64 + (k ^ (hh & 31));
            sWr[col] = Wrel[r * 4096 + idx];
            sWg[col] = Wgate[r * 4096 + idx];
        }
        for (int idx = tid; idx < 2048; idx += 256) {
            int nl = idx >> 6, hh = idx & 63;
            int n = n0 + nl;
            sT[idx] = (n < NN) ? g_t[((size_t)n * RR + r) * 64 + hh] : 0.f;
        }
        __syncthreads();

        float ag0[4] = {0.f,0.f,0.f,0.f}, ag1[4] = {0.f,0.f,0.f,0.f};
        float gd0[4] = {0.f,0.f,0.f,0.f}, gd1[4] = {0.f,0.f,0.f,0.f};
#pragma unroll 4
        for (int hh = 0; hh < 64; hh++) {
            int c = hh * 64 + (tx ^ (hh & 31));
            float wr0 = sWr[c], wr1 = sWr[c + 32];
            float wg0 = sWg[c], wg1 = sWg[c + 32];
#pragma unroll
            for (int j = 0; j < 4; j++) {
                float tv = sT[(ty + 8 * j) * 64 + hh];
                float hv = sH[(ty + 8 * j) * 64 + hh];
                ag0[j] += tv * wr0;  ag1[j] += tv * wr1;
                gd0[j] += hv * wg0;  gd1[j] += hv * wg1;
            }
        }
        float bg0 = __ldg(&bgate[r * 64 + tx]);
        float bg1 = __ldg(&bgate[r * 64 + tx + 32]);
#pragma unroll
        for (int j = 0; j < 4; j++) {
            float g0 = 1.f / (1.f + expf(-(gd0[j] + bg0)));
            float g1 = 1.f / (1.f + expf(-(gd1[j] + bg1)));
            acc0[j] += g0 * ag0[j];
            acc1[j] += g1 * ag1[j];
        }
    }

    // residual + LayerNorm + relu (each warp owns full 64-dim rows: 2 values/lane)
    float ga0 = __ldg(&gamma[tx]), ga1 = __ldg(&gamma[tx + 32]);
    float be0 = __ldg(&beta[tx]),  be1 = __ldg(&beta[tx + 32]);
#pragma unroll
    for (int j = 0; j < 4; j++) {
        int nl = ty + 8 * j;
        int n = n0 + nl;
        float v0 = sH[nl * 64 + tx]      + acc0[j] * 0.125f;
        float v1 = sH[nl * 64 + tx + 32] + acc1[j] * 0.125f;
        float s = v0 + v1;
#pragma unroll
        for (int o = 16; o > 0; o >>= 1) s += __shfl_xor_sync(0xffffffffu, s, o);
        float mu = s * (1.f / 64.f);
        float d0 = v0 - mu, d1 = v1 - mu;
        float q = d0 * d0 + d1 * d1;
#pragma unroll
        for (int o = 16; o > 0; o >>= 1) q += __shfl_xor_sync(0xffffffffu, q, o);
        float inv = rsqrtf(q * (1.f / 64.f) + 1e-5f);
        if (n < NN) {
            float o0 = d0 * inv * ga0 + be0;
            float o1 = d1 * inv * ga1 + be1;
            hout[n * 64 + tx]      = fmaxf(o0, 0.f);
            hout[n * 64 + tx + 32] = fmaxf(o1, 0.f);
        }
    }
}

// ---------------- launch ----------------
extern "C" void kernel_launch(void* const* d_in, const int* in_sizes, int n_in,
                              void* d_out, int out_size)
{
    const float* x      = (const float*)d_in[0];
    const int*   ei     = (const int*)d_in[1];
    const int*   et     = (const int*)d_in[2];
    const float* W_in   = (const float*)d_in[3];
    const float* b_in   = (const float*)d_in[4];
    const float* W_rel  = (const float*)d_in[5];
    const float* W_gate = (const float*)d_in[6];
    const float* b_gate = (const float*)d_in[7];
    const float* W_att  = (const float*)d_in[8];
    const float* b_att  = (const float*)d_in[9];
    const float* ln_g   = (const float*)d_in[10];
    const float* ln_b   = (const float*)d_in[11];
    const float* W_out  = (const float*)d_in[12];
    const float* b_out  = (const float*)d_in[13];
    float* out = (float*)d_out;

    float *h0, *h1;
    cudaGetSymbolAddress((void**)&h0, g_h0);
    cudaGetSymbolAddress((void**)&h1, g_h1);

    const int gN = (NN + 31) / 32;              // 1563
    const int gZ = (NN * RR * HH / 4) / 256;    // 25000
    const int gP = (NN + 7) / 8;                // 6250
    const int gE = (EE + 255) / 256;            // 3125
    const int gS = (EE + 15) / 16;              // 50000

    k_gemm64<<<gN, 256>>>(x, W_in, b_in, h0, NN, 1);

    float* hc = h0;
    float* hn = h1;
    for (int l = 0; l < LL; l++) {
        k_zero<<<gZ, 256>>>();
        k_proj<<<gP, 128>>>(hc, W_att);
        k_scores<<<gE, 256>>>(ei, et, b_att);
        k_exp<<<gE, 256>>>(et);
        k_scatter<<<gS, 256>>>(ei, et, hc);
        k_combine<<<gN, 256>>>(hc, W_rel, W_gate, b_gate,
                               ln_g + l * 64, ln_b + l * 64, hn);
        float* tmp = hc; hc = hn; hn = tmp;
    }

    k_gemm64<<<gN, 256>>>(hc, W_out, b_out, out, NN, 0);
}

// round 3
// speedup vs baseline: 1.8006x; 1.8006x over previous
#include <cuda_runtime.h>
#include <cuda_bf16.h>

#define NN 50000
#define EE 800000
#define HH 64
#define RR 8
#define LL 3

// ---------------- scratch (static __device__, no allocs) ----------------
__device__ __align__(16) float g_h0[NN * HH];
__device__ __align__(16) float g_h1[NN * HH];
__device__ __align__(16) __nv_bfloat16 g_h0b[NN * HH];
__device__ __align__(16) __nv_bfloat16 g_h1b[NN * HH];
__device__ float g_asrc[NN * RR];
__device__ float g_adst[NN * RR];
__device__ __align__(16) __nv_bfloat16 g_t[NN * RR * HH];   // 51.2 MB, ~L2-resident
__device__ unsigned g_max16[16];
__device__ float g_denom[RR];
__device__ float g_shift[RR];
__device__ unsigned g_wrelb[RR * 32 * 64];   // bf16x2 pairs, [r][kp][n]
__device__ unsigned g_wgtb[RR * 32 * 64];

// monotonic float<->uint encoding for atomicMax over signed floats
__device__ __forceinline__ unsigned fenc(float f) {
    unsigned u = __float_as_uint(f);
    return (u & 0x80000000u) ? ~u : (u | 0x80000000u);
}
__device__ __forceinline__ float fdec(unsigned u) {
    unsigned b = (u & 0x80000000u) ? (u ^ 0x80000000u) : ~u;
    return __uint_as_float(b);
}

__device__ __forceinline__ void red4(__nv_bfloat16* p, uint4 v) {
    asm volatile("red.global.add.noftz.v4.bf16x2 [%0], {%1,%2,%3,%4};"
                 :: "l"(p), "r"(v.x), "r"(v.y), "r"(v.z), "r"(v.w) : "memory");
}

__device__ __forceinline__ uint4 scl4(uint4 u, __nv_bfloat162 e) {
    __nv_bfloat162* pv = reinterpret_cast<__nv_bfloat162*>(&u);
    pv[0] = __hmul2(pv[0], e); pv[1] = __hmul2(pv[1], e);
    pv[2] = __hmul2(pv[2], e); pv[3] = __hmul2(pv[3], e);
    return u;
}

__device__ __forceinline__ void mma16816(float* c, const unsigned* a, unsigned b0, unsigned b1) {
    asm volatile(
        "mma.sync.aligned.m16n8k16.row.col.f32.bf16.bf16.f32 "
        "{%0,%1,%2,%3},{%4,%5,%6,%7},{%8,%9},{%0,%1,%2,%3};"
        : "+f"(c[0]), "+f"(c[1]), "+f"(c[2]), "+f"(c[3])
        : "r"(a[0]), "r"(a[1]), "r"(a[2]), "r"(a[3]), "r"(b0), "r"(b1));
}

// ---------------- zero t buffer + stats ----------------
__global__ void k_zero() {
    size_t i = (size_t)blockIdx.x * 256 + threadIdx.x;   // 12500*256 uint4 = 25.6M bf16
    ((uint4*)g_t)[i] = make_uint4(0, 0, 0, 0);
    if (blockIdx.x == 0) {
        if (threadIdx.x < 16) g_max16[threadIdx.x] = 0u;
        if (threadIdx.x < 8)  g_denom[threadIdx.x] = 0.f;
    }
}

// ---------------- convert weights to bf16x2 mma-B layout: [r][kp][n] ----------------
__global__ void k_cvtw(const float* __restrict__ Wr, const float* __restrict__ Wg) {
    int idx = blockIdx.x * 256 + threadIdx.x;   // 16384 = 8*32*64
    int n = idx & 63, kp = (idx >> 6) & 31, r = idx >> 11;
    const float* a = Wr + r * 4096 + n * 64 + kp * 2;
    __nv_bfloat162 v = __floats2bfloat162_rn(a[0], a[1]);
    g_wrelb[idx] = *reinterpret_cast<unsigned*>(&v);
    const float* b = Wg + r * 4096 + n * 64 + kp * 2;
    __nv_bfloat162 w = __floats2bfloat162_rn(b[0], b[1]);
    g_wgtb[idx] = *reinterpret_cast<unsigned*>(&w);
}

// ---------------- generic fp32 64x64 GEMM (input / output projections) ----------------
__global__ void k_gemm64(const float* __restrict__ A, const float* __restrict__ W,
                         const float* __restrict__ b, float* __restrict__ out,
                         __nv_bfloat16* __restrict__ obf, int nrows, int do_relu)
{
    __shared__ float sW[64 * 64];
    __shared__ float sA[32 * 64];
    int tid = threadIdx.x;
    int n0 = blockIdx.x * 32;

    for (int idx = tid; idx < 4096; idx += 256) {
        int k = idx >> 6, h = idx & 63;
        sW[h * 64 + (k ^ (h & 31))] = W[idx];
    }
    for (int idx = tid; idx < 2048; idx += 256) {
        int nl = idx >> 6, h = idx & 63;
        int n = n0 + nl;
        sA[idx] = (n < nrows) ? A[n * 64 + h] : 0.f;
    }
    __syncthreads();

    int tx = tid & 31, ty = tid >> 5;
    float a0[4] = {0.f, 0.f, 0.f, 0.f}, a1[4] = {0.f, 0.f, 0.f, 0.f};
#pragma unroll 4
    for (int h = 0; h < 64; h++) {
        int c = h * 64 + (tx ^ (h & 31));
        float w0 = sW[c];
        float w1 = sW[c + 32];
#pragma unroll
        for (int j = 0; j < 4; j++) {
            float av = sA[(ty + 8 * j) * 64 + h];
            a0[j] += av * w0;
            a1[j] += av * w1;
        }
    }
    float b0 = __ldg(&b[tx]), b1 = __ldg(&b[tx + 32]);
#pragma unroll
    for (int j = 0; j < 4; j++) {
        int n = n0 + ty + 8 * j;
        if (n < nrows) {
            float v0 = a0[j] + b0, v1 = a1[j] + b1;
            if (do_relu) { v0 = fmaxf(v0, 0.f); v1 = fmaxf(v1, 0.f); }
            out[n * 64 + tx]      = v0;
            out[n * 64 + tx + 32] = v1;
            if (obf) {
                obf[n * 64 + tx]      = __float2bfloat16(v0);
                obf[n * 64 + tx + 32] = __float2bfloat16(v1);
            }
        }
    }
}

// ---------------- per-node attention projections + per-relation maxima ----------------
__global__ void k_proj(const float* __restrict__ h, const float* __restrict__ Watt)
{
    __shared__ float sH[8 * 64];
    __shared__ float sW[64 * 16];
    __shared__ unsigned smax[16];
    int tid = threadIdx.x;
    int n0 = blockIdx.x * 8;

    if (tid < 16) smax[tid] = 0u;
    for (int idx = tid; idx < 512; idx += 128) {
        int nl = idx >> 6, hh = idx & 63;
        int n = n0 + nl;
        sH[idx] = (n < NN) ? h[n * 64 + hh] : 0.f;
    }
    for (int idx = tid; idx < 1024; idx += 128) {
        int p = idx >> 6, hh = idx & 63;
        sW[hh * 16 + p] = Watt[(p & 7) * 128 + (p >> 3) * 64 + hh];
    }
    __syncthreads();

    int nl = tid >> 4, p = tid & 15;
    float acc = 0.f;
#pragma unroll 8
    for (int hh = 0; hh < 64; hh++)
        acc += sH[nl * 64 + hh] * sW[hh * 16 + p];

    int n = n0 + nl;
    if (n < NN) {
        int r = p & 7;
        if (p < 8) g_asrc[n * RR + r] = acc;
        else       g_adst[n * RR + r] = acc;
        atomicMax(&smax[p], fenc(acc));
    }
    __syncthreads();
    if (tid < 16) atomicMax(&g_max16[tid], smax[tid]);
}

// ---------------- per-relation softmax shift (upper bound; softmax shift-invariant) ----
__global__ void k_prep(const float* __restrict__ batt) {
    int r = threadIdx.x;
    if (r < RR) {
        float c = fdec(g_max16[r]) + fdec(g_max16[8 + r]) + batt[r];
        g_shift[r] = (c > 0.f) ? c : 0.2f * c;   // bound passes through monotone leaky-relu
    }
}

// ---------------- fused edge pass: score -> exp -> denom + scatter ex*h[src] ----------
__global__ void k_edge(const int* __restrict__ ei, const int* __restrict__ et,
                       const float* __restrict__ batt, const __nv_bfloat16* __restrict__ hbf)
{
    __shared__ float s_ex[64];
    __shared__ int s_src[64];
    __shared__ int s_dstr[64];
    __shared__ float s_den[8];
    int tid = threadIdx.x;
    if (tid < 8) s_den[tid] = 0.f;
    __syncthreads();

    if (tid < 64) {
        int e = blockIdx.x * 64 + tid;   // EE == 12500*64 exactly
        int s = ei[e], d = ei[EE + e], r = et[e];
        float sc = g_asrc[s * RR + r] + g_adst[d * RR + r] + __ldg(&batt[r]);
        sc = (sc > 0.f) ? sc : 0.2f * sc;
        float ex = __expf(sc - g_shift[r]);
        s_ex[tid] = ex;
        s_src[tid] = s;
        s_dstr[tid] = d * RR + r;
        atomicAdd(&s_den[r], ex);
    }
    __syncthreads();
    if (tid < 8) atomicAdd(&g_denom[tid], s_den[tid]);

    int j = tid & 63, p = tid >> 6;       // 4 threads per edge, 32B each
    int s = s_src[j];
    __nv_bfloat162 exb = __float2bfloat162_rn(s_ex[j]);
    const uint4* hp = (const uint4*)(hbf + (size_t)s * 64);
    uint4 u0 = scl4(hp[p * 2], exb);
    uint4 u1 = scl4(hp[p * 2 + 1], exb);
    __nv_bfloat16* dst = g_t + (size_t)s_dstr[j] * 64 + p * 16;
    red4(dst, u0);
    red4(dst + 8, u1);
}

// ---------------- fused combine: bf16 mma GEMMs + gate + mean + residual + LN + relu ---
__global__ void __launch_bounds__(256, 2)
k_comb(const float* __restrict__ h32, const __nv_bfloat16* __restrict__ hbf,
       const float* __restrict__ bgate,
       const float* __restrict__ gamma, const float* __restrict__ beta,
       float* __restrict__ hout, __nv_bfloat16* __restrict__ houtbf)
{
    __shared__ unsigned sT[128 * 32];      // t tile, swizzled b32 words
    __shared__ unsigned sH[128 * 32];      // hbf tile, swizzled
    __shared__ unsigned sB[2 * 32 * 64];   // per-relation Wrel | Wgate, swizzled

    int tid = threadIdx.x, lane = tid & 31, wid = tid >> 5;
    int n0 = blockIdx.x * 128;
    int lr = lane >> 2, lc = lane & 3;

    // load h tile once
    for (int i = tid; i < 1024; i += 256) {
        int row = i >> 3, q = i & 7;
        uint4 u = make_uint4(0, 0, 0, 0);
        if (n0 + row < NN) u = ((const uint4*)(hbf + (size_t)(n0 + row) * 64))[q];
        *(uint4*)&sH[row * 32 + ((q * 4) ^ ((row & 7) << 2))] = u;
    }
    __syncthreads();

    int arow = wid * 16 + lr;
    int ax = (arow & 7) << 2;
    unsigned ha[16];
#pragma unroll
    for (int kc = 0; kc < 4; kc++) {
        int w0 = lc + kc * 8, w1 = w0 + 4;
        ha[kc * 4 + 0] = sH[arow * 32       + (w0 ^ ax)];
        ha[kc * 4 + 1] = sH[(arow + 8) * 32 + (w0 ^ ax)];
        ha[kc * 4 + 2] = sH[arow * 32       + (w1 ^ ax)];
        ha[kc * 4 + 3] = sH[(arow + 8) * 32 + (w1 ^ ax)];
    }

    float acc[32];
#pragma unroll
    for (int i = 0; i < 32; i++) acc[i] = 0.f;

    for (int r = 0; r < RR; r++) {
        __syncthreads();
        for (int i = tid; i < 512; i += 256) {          // weights: 2 x 512 uint4
            int kp = i >> 4, q = i & 15;
            int dw = kp * 64 + ((q * 4) ^ ((kp & 3) << 3));
            *(uint4*)&sB[dw]        = ((const uint4*)(g_wrelb + r * 2048))[i];
            *(uint4*)&sB[2048 + dw] = ((const uint4*)(g_wgtb  + r * 2048))[i];
        }
        for (int i = tid; i < 1024; i += 256) {         // t tile for this r
            int row = i >> 3, q = i & 7;
            uint4 u = make_uint4(0, 0, 0, 0);
            if (n0 + row < NN)
                u = ((const uint4*)(g_t + ((size_t)(n0 + row) * RR + r) * 64))[q];
            *(uint4*)&sT[row * 32 + ((q * 4) ^ ((row & 7) << 2))] = u;
        }
        __syncthreads();

        unsigned ta[16];
#pragma unroll
        for (int kc = 0; kc < 4; kc++) {
            int w0 = lc + kc * 8, w1 = w0 + 4;
            ta[kc * 4 + 0] = sT[arow * 32       + (w0 ^ ax)];
            ta[kc * 4 + 1] = sT[(arow + 8) * 32 + (w0 ^ ax)];
            ta[kc * 4 + 2] = sT[arow * 32       + (w1 ^ ax)];
            ta[kc * 4 + 3] = sT[(arow + 8) * 32 + (w1 ^ ax)];
        }
        float invd = 1.f / (g_denom[r] * 8.f);

#pragma unroll
        for (int j = 0; j < 8; j++) {
            float gC[4] = {0, 0, 0, 0}, aC[4] = {0, 0, 0, 0};
#pragma unroll
            for (int kc = 0; kc < 4; kc++) {
                int kp0 = lc + kc * 8;
                int nsw = (j * 8 + lr) ^ (lc << 3);
                int bw0 = kp0 * 64 + nsw;
                int bw1 = (kp0 + 4) * 64 + nsw;
                mma16816(aC, &ta[kc * 4], sB[bw0], sB[bw1]);
                mma16816(gC, &ha[kc * 4], sB[2048 + bw0], sB[2048 + bw1]);
            }
            float bg0 = __ldg(&bgate[r * 64 + j * 8 + lc * 2]);
            float bg1 = __ldg(&bgate[r * 64 + j * 8 + lc * 2 + 1]);
#pragma unroll
            for (int q = 0; q < 4; q++) {
                float x = gC[q] + ((q & 1) ? bg1 : bg0);
                float g = 1.f / (1.f + __expf(-x));
                acc[j * 4 + q] += g * aC[q] * invd;
            }
        }
    }

    // epilogue: residual + LN + relu, two node-rows per lane-group
#pragma unroll
    for (int half = 0; half < 2; half++) {
        int node = n0 + wid * 16 + lr + half * 8;
        float v[16];
#pragma unroll
        for (int j = 0; j < 8; j++) {
            float2 hv = make_float2(0.f, 0.f);
            if (node < NN) hv = *(const float2*)(h32 + (size_t)node * 64 + j * 8 + lc * 2);
            v[j * 2 + 0] = hv.x + acc[j * 4 + half * 2 + 0];
            v[j * 2 + 1] = hv.y + acc[j * 4 + half * 2 + 1];
        }
        float s = 0.f;
#pragma unroll
        for (int i = 0; i < 16; i++) s += v[i];
        s += __shfl_xor_sync(0xffffffffu, s, 1);
        s += __shfl_xor_sync(0xffffffffu, s, 2);
        float mu = s * (1.f / 64.f);
        float q2 = 0.f;
#pragma unroll
        for (int i = 0; i < 16; i++) { float d = v[i] - mu; q2 += d * d; }
        q2 += __shfl_xor_sync(0xffffffffu, q2, 1);
        q2 += __shfl_xor_sync(0xffffffffu, q2, 2);
        float inv = rsqrtf(q2 * (1.f / 64.f) + 1e-5f);
        if (node < NN) {
#pragma unroll
            for (int j = 0; j < 8; j++) {
                int col = j * 8 + lc * 2;
                float o0 = (v[j * 2 + 0] - mu) * inv * __ldg(&gamma[col])     + __ldg(&beta[col]);
                float o1 = (v[j * 2 + 1] - mu) * inv * __ldg(&gamma[col + 1]) + __ldg(&beta[col + 1]);
                o0 = fmaxf(o0, 0.f); o1 = fmaxf(o1, 0.f);
                *(float2*)(hout + (size_t)node * 64 + col) = make_float2(o0, o1);
                __nv_bfloat162 ob = __floats2bfloat162_rn(o0, o1);
                *(__nv_bfloat162*)(houtbf + (size_t)node * 64 + col) = ob;
            }
        }
    }
}

// ---------------- launch ----------------
extern "C" void kernel_launch(void* const* d_in, const int* in_sizes, int n_in,
                              void* d_out, int out_size)
{
    const float* x      = (const float*)d_in[0];
    const int*   ei     = (const int*)d_in[1];
    const int*   et     = (const int*)d_in[2];
    const float* W_in   = (const float*)d_in[3];
    const float* b_in   = (const float*)d_in[4];
    const float* W_rel  = (const float*)d_in[5];
    const float* W_gate = (const float*)d_in[6];
    const float* b_gate = (const float*)d_in[7];
    const float* W_att  = (const float*)d_in[8];
    const float* b_att  = (const float*)d_in[9];
    const float* ln_g   = (const float*)d_in[10];
    const float* ln_b   = (const float*)d_in[11];
    const float* W_out  = (const float*)d_in[12];
    const float* b_out  = (const float*)d_in[13];
    float* out = (float*)d_out;

    float *h0, *h1;
    __nv_bfloat16 *h0b, *h1b;
    cudaGetSymbolAddress((void**)&h0, g_h0);
    cudaGetSymbolAddress((void**)&h1, g_h1);
    cudaGetSymbolAddress((void**)&h0b, g_h0b);
    cudaGetSymbolAddress((void**)&h1b, g_h1b);

    const int gN = (NN + 31) / 32;      // 1563
    const int gC = (NN + 127) / 128;    // 391
    const int gZ = 12500;
    const int gP = (NN + 7) / 8;        // 6250
    const int gE = 12500;

    k_cvtw<<<64, 256>>>(W_rel, W_gate);
    k_gemm64<<<gN, 256>>>(x, W_in, b_in, h0, h0b, NN, 1);

    float* hc = h0;  __nv_bfloat16* hcb = h0b;
    float* hn = h1;  __nv_bfloat16* hnb = h1b;
    for (int l = 0; l < LL; l++) {
        k_zero<<<gZ, 256>>>();
        k_proj<<<gP, 128>>>(hc, W_att);
        k_prep<<<1, 32>>>(b_att);
        k_edge<<<gE, 256>>>(ei, et, b_att, hcb);
        k_comb<<<gC, 256>>>(hc, hcb, b_gate, ln_g + l * 64, ln_b + l * 64, hn, hnb);
        float* t = hc; hc = hn; hn = t;
        __nv_bfloat16* tb = hcb; hcb = hnb; hnb = tb;
    }

    k_gemm64<<<gN, 256>>>(hc, W_out, b_out, out, nullptr, NN, 0);
}